// round 2
// baseline (speedup 1.0000x reference)
#include <cuda_runtime.h>
#include <cuda_bf16.h>

#define Bv      2
#define Sv      4096
#define QKVD    2048
#define NHEAD   16
#define NKVH    8
#define HDIM    64
#define NFEAT   64
#define CHUNK   128
#define NCHUNK  32
#define MROWS   (Bv*Sv)

// ---------------- scratch (device globals; no allocs allowed) ----------------
__device__ float g_qkv [(size_t)MROWS*QKVD];
__device__ float g_qp  [(size_t)MROWS*NHEAD*NFEAT];
__device__ float g_kp  [(size_t)MROWS*NKVH*NFEAT];
__device__ float g_z   [(size_t)Bv*NKVH*Sv];
__device__ float g_kvc [(size_t)Bv*NKVH*NCHUNK*NFEAT*HDIM];
__device__ float g_attn[(size_t)MROWS*(NHEAD*HDIM)];

// ---------------- C[M,N] = A[M,K] * B[N,K]^T, 128x128x16 tiles ----------------
__global__ void __launch_bounds__(256) gemm_nt_kernel(
    const float* __restrict__ A, const float* __restrict__ B,
    float* __restrict__ C, int M, int N, int K)
{
    __shared__ float As[2][16][132];
    __shared__ float Bs[2][16][132];
    const int tid = threadIdx.x;
    const int tx = tid & 15, ty = tid >> 4;
    const int m0 = blockIdx.y * 128, n0 = blockIdx.x * 128;
    const int r0 = tid >> 2, r1 = r0 + 64;
    const int kq0 = (tid & 3) * 4;

    float4 ra0, ra1, rb0, rb1;
    ra0 = *(const float4*)(A + (size_t)(m0 + r0) * K + kq0);
    ra1 = *(const float4*)(A + (size_t)(m0 + r1) * K + kq0);
    rb0 = *(const float4*)(B + (size_t)(n0 + r0) * K + kq0);
    rb1 = *(const float4*)(B + (size_t)(n0 + r1) * K + kq0);
    As[0][kq0+0][r0]=ra0.x; As[0][kq0+1][r0]=ra0.y; As[0][kq0+2][r0]=ra0.z; As[0][kq0+3][r0]=ra0.w;
    As[0][kq0+0][r1]=ra1.x; As[0][kq0+1][r1]=ra1.y; As[0][kq0+2][r1]=ra1.z; As[0][kq0+3][r1]=ra1.w;
    Bs[0][kq0+0][r0]=rb0.x; Bs[0][kq0+1][r0]=rb0.y; Bs[0][kq0+2][r0]=rb0.z; Bs[0][kq0+3][r0]=rb0.w;
    Bs[0][kq0+0][r1]=rb1.x; Bs[0][kq0+1][r1]=rb1.y; Bs[0][kq0+2][r1]=rb1.z; Bs[0][kq0+3][r1]=rb1.w;
    __syncthreads();

    float acc[8][8];
    #pragma unroll
    for (int i = 0; i < 8; i++)
        #pragma unroll
        for (int j = 0; j < 8; j++) acc[i][j] = 0.f;

    const int nkt = K >> 4;
    int buf = 0;
    for (int kt = 0; kt < nkt; kt++) {
        if (kt + 1 < nkt) {
            const int kb = (kt + 1) << 4;
            ra0 = *(const float4*)(A + (size_t)(m0 + r0) * K + kb + kq0);
            ra1 = *(const float4*)(A + (size_t)(m0 + r1) * K + kb + kq0);
            rb0 = *(const float4*)(B + (size_t)(n0 + r0) * K + kb + kq0);
            rb1 = *(const float4*)(B + (size_t)(n0 + r1) * K + kb + kq0);
        }
        #pragma unroll
        for (int k = 0; k < 16; k++) {
            float4 a0 = *(const float4*)&As[buf][k][ty*8];
            float4 a1 = *(const float4*)&As[buf][k][ty*8+4];
            float4 b0 = *(const float4*)&Bs[buf][k][tx*8];
            float4 b1 = *(const float4*)&Bs[buf][k][tx*8+4];
            float av[8] = {a0.x,a0.y,a0.z,a0.w,a1.x,a1.y,a1.z,a1.w};
            float bv[8] = {b0.x,b0.y,b0.z,b0.w,b1.x,b1.y,b1.z,b1.w};
            #pragma unroll
            for (int i = 0; i < 8; i++)
                #pragma unroll
                for (int j = 0; j < 8; j++)
                    acc[i][j] = fmaf(av[i], bv[j], acc[i][j]);
        }
        if (kt + 1 < nkt) {
            const int nb = buf ^ 1;
            As[nb][kq0+0][r0]=ra0.x; As[nb][kq0+1][r0]=ra0.y; As[nb][kq0+2][r0]=ra0.z; As[nb][kq0+3][r0]=ra0.w;
            As[nb][kq0+0][r1]=ra1.x; As[nb][kq0+1][r1]=ra1.y; As[nb][kq0+2][r1]=ra1.z; As[nb][kq0+3][r1]=ra1.w;
            Bs[nb][kq0+0][r0]=rb0.x; Bs[nb][kq0+1][r0]=rb0.y; Bs[nb][kq0+2][r0]=rb0.z; Bs[nb][kq0+3][r0]=rb0.w;
            Bs[nb][kq0+0][r1]=rb1.x; Bs[nb][kq0+1][r1]=rb1.y; Bs[nb][kq0+2][r1]=rb1.z; Bs[nb][kq0+3][r1]=rb1.w;
        }
        __syncthreads();
        buf ^= 1;
    }

    #pragma unroll
    for (int i = 0; i < 8; i++) {
        float4 c0 = {acc[i][0], acc[i][1], acc[i][2], acc[i][3]};
        float4 c1 = {acc[i][4], acc[i][5], acc[i][6], acc[i][7]};
        float* cp = C + (size_t)(m0 + ty*8 + i) * N + n0 + tx*8;
        *(float4*)cp       = c0;
        *(float4*)(cp + 4) = c1;
    }
}

// ---------------- RoPE + relu feature projection (q and k heads) -------------
__global__ void __launch_bounds__(256) ropeproj_kernel(
    const float* __restrict__ cosg, const float* __restrict__ sing,
    const float* __restrict__ proj)
{
    __shared__ float dat[64*68];   // [d][r]
    __shared__ float pj [64*68];   // [d][f]
    const int tid = threadIdx.x;
    const int rbase = blockIdx.x * 64;

    #pragma unroll
    for (int j = 0; j < 16; j++) {
        int i = tid + j*256;
        int f = i >> 6, d = i & 63;
        pj[d*68 + f] = proj[i];
    }
    #pragma unroll
    for (int j = 0; j < 16; j++) {
        int e = tid + j*256;
        int r = e >> 6, d = e & 63;
        int rho = rbase + r;
        int bs  = rho / 24;
        int h   = rho - bs*24;
        int s   = bs & (Sv-1);
        size_t base = (size_t)bs*QKVD + h*64;
        float val  = g_qkv[base + d];
        int   pd   = (d < 32) ? d + 32 : d - 32;
        float part = g_qkv[base + pd];
        float rot  = (d < 32) ? -part : part;
        dat[d*68 + r] = fmaf(val, cosg[s*64 + d], rot * sing[s*64 + d]);
    }
    __syncthreads();

    const int rq = tid >> 4, fq = tid & 15;
    float acc[4][4];
    #pragma unroll
    for (int i = 0; i < 4; i++)
        #pragma unroll
        for (int j = 0; j < 4; j++) acc[i][j] = 0.f;

    #pragma unroll
    for (int k = 0; k < 64; k++) {
        float4 a = *(const float4*)&dat[k*68 + rq*4];
        float4 b = *(const float4*)&pj [k*68 + fq*4];
        float av[4] = {a.x,a.y,a.z,a.w};
        float bv[4] = {b.x,b.y,b.z,b.w};
        #pragma unroll
        for (int i = 0; i < 4; i++)
            #pragma unroll
            for (int j = 0; j < 4; j++)
                acc[i][j] = fmaf(av[i], bv[j], acc[i][j]);
    }

    const float ratio = (float)(0.125 * (0.125 + 1e-4));
    #pragma unroll
    for (int i = 0; i < 4; i++) {
        int rho = rbase + rq*4 + i;
        int bs  = rho / 24;
        int h   = rho - bs*24;
        float4 o;
        o.x = fmaxf(acc[i][0]*ratio, 0.f);
        o.y = fmaxf(acc[i][1]*ratio, 0.f);
        o.z = fmaxf(acc[i][2]*ratio, 0.f);
        o.w = fmaxf(acc[i][3]*ratio, 0.f);
        if (h < NHEAD) {
            o.x += 1e-4f; o.y += 1e-4f; o.z += 1e-4f; o.w += 1e-4f;
            *(float4*)&g_qp[((size_t)bs*NHEAD + h)*NFEAT + fq*4] = o;
        } else {
            *(float4*)&g_kp[((size_t)bs*NKVH + (h - NHEAD))*NFEAT + fq*4] = o;
        }
    }
}

// ---------------- inclusive prefix of rowsum(kp) over t, per (b,kvh) ---------
__global__ void __launch_bounds__(128) zscan_kernel()
{
    const int bkv = blockIdx.x;
    const int b   = bkv >> 3, kvh = bkv & 7;
    const int tid = threadIdx.x;
    const int lane = tid & 31, warp = tid >> 5;
    __shared__ float wsum[4];
    float carry = 0.f;

    for (int tile = 0; tile < 32; tile++) {
        int t = tile*128 + tid;
        const float* row = g_kp + (((size_t)(b*Sv + t))*NKVH + kvh)*NFEAT;
        float s = 0.f;
        #pragma unroll
        for (int f = 0; f < 64; f += 4) {
            float4 v = *(const float4*)(row + f);
            s += (v.x + v.y) + (v.z + v.w);
        }
        float x = s;
        #pragma unroll
        for (int o = 1; o < 32; o <<= 1) {
            float n = __shfl_up_sync(0xffffffffu, x, o);
            if (lane >= o) x += n;
        }
        if (lane == 31) wsum[warp] = x;
        __syncthreads();
        float off = carry;
        for (int w2 = 0; w2 < warp; w2++) off += wsum[w2];
        g_z[(size_t)bkv*Sv + t] = off + x;
        carry += wsum[0] + wsum[1] + wsum[2] + wsum[3];
        __syncthreads();
    }
}

// ---------------- per-chunk KV = Kp^T V (64x64) ------------------------------
__global__ void __launch_bounds__(256) chunkkv_kernel()
{
    extern __shared__ float cs[];
    float* Ks = cs;            // [t][f]
    float* Vs = cs + 8192;     // [t][d]
    const int c   = blockIdx.x;
    const int bkv = blockIdx.y;
    const int b   = bkv >> 3, kvh = bkv & 7;
    const int tid = threadIdx.x;

    #pragma unroll
    for (int j = 0; j < 32; j++) {
        int e = tid + j*256;
        int t = e >> 6, f = e & 63;
        size_t bs = (size_t)(b*Sv + c*CHUNK + t);
        Ks[e] = g_kp[(bs*NKVH + kvh)*NFEAT + f];
        Vs[e] = g_qkv[bs*QKVD + 1536 + kvh*64 + f];
    }
    __syncthreads();

    const int fq = tid >> 4, dq = tid & 15;
    float acc[4][4];
    #pragma unroll
    for (int i = 0; i < 4; i++)
        #pragma unroll
        for (int j = 0; j < 4; j++) acc[i][j] = 0.f;

    #pragma unroll 8
    for (int t = 0; t < 128; t++) {
        float4 a = *(const float4*)&Ks[t*64 + fq*4];
        float4 v = *(const float4*)&Vs[t*64 + dq*4];
        float av[4] = {a.x,a.y,a.z,a.w};
        #pragma unroll
        for (int i = 0; i < 4; i++) {
            acc[i][0] = fmaf(av[i], v.x, acc[i][0]);
            acc[i][1] = fmaf(av[i], v.y, acc[i][1]);
            acc[i][2] = fmaf(av[i], v.z, acc[i][2]);
            acc[i][3] = fmaf(av[i], v.w, acc[i][3]);
        }
    }
    size_t base = ((size_t)bkv*NCHUNK + c)*4096;
    #pragma unroll
    for (int i = 0; i < 4; i++) {
        float4 o = {acc[i][0], acc[i][1], acc[i][2], acc[i][3]};
        *(float4*)&g_kvc[base + (size_t)(fq*4 + i)*64 + dq*4] = o;
    }
}

// ---------------- exclusive chunk-prefix of KV, in place ---------------------
__global__ void __launch_bounds__(256) kvprefix_kernel()
{
    const int bkv = blockIdx.x;
    const int tid = threadIdx.x;
    float acc[16];
    #pragma unroll
    for (int j = 0; j < 16; j++) acc[j] = 0.f;
    for (int c = 0; c < NCHUNK; c++) {
        size_t base = ((size_t)bkv*NCHUNK + c)*4096;
        #pragma unroll
        for (int j = 0; j < 16; j++) {
            size_t idx = base + tid + j*256;
            float cur = g_kvc[idx];
            g_kvc[idx] = acc[j];
            acc[j] += cur;
        }
    }
}

// ---------------- stage D: intra-chunk causal + prefix term ------------------
#define SD_FLOATS (64*132 + 64*132 + 128*132 + 128*64 + 64*64 + 128)
#define SD_BYTES  (SD_FLOATS*4)

__global__ void __launch_bounds__(256) stage_d_kernel()
{
    extern __shared__ float sm[];
    float* Qt   = sm;                  // [f][t] 64x132
    float* Kt   = Qt  + 64*132;        // [f][t] 64x132
    float* Ss   = Kt  + 64*132;        // [t][t'] 128x132
    float* Vs   = Ss  + 128*132;       // [t'][d] 128x64
    float* KVs  = Vs  + 128*64;        // [f][d]  64x64
    float* dinv = KVs + 64*64;         // [t] 128

    const int c   = blockIdx.x;
    const int h   = blockIdx.y;
    const int b   = blockIdx.z;
    const int kvh = h >> 1;
    const int tid = threadIdx.x;
    const size_t t0 = (size_t)b*Sv + c*CHUNK;

    #pragma unroll
    for (int j = 0; j < 32; j++) {
        int e = tid + j*256;
        int t = e >> 6, f = e & 63;
        Qt[f*132 + t] = g_qp[((t0 + t)*NHEAD + h)*NFEAT + f];
        Kt[f*132 + t] = g_kp[((t0 + t)*NKVH + kvh)*NFEAT + f];
        Vs[e]         = g_qkv[(t0 + t)*QKVD + 1536 + kvh*64 + f];
    }
    #pragma unroll
    for (int j = 0; j < 16; j++) {
        int e = tid + j*256;
        KVs[e] = g_kvc[(((size_t)(b*NKVH + kvh))*NCHUNK + c)*4096 + e];
    }
    __syncthreads();

    if (tid < 128) {
        float s = 0.f;
        #pragma unroll
        for (int f = 0; f < 64; f++) s += Qt[f*132 + tid];
        float z = g_z[((size_t)(b*NKVH + kvh))*Sv + c*CHUNK + tid];
        dinv[tid] = 1.0f / (s*z + 1e-6f);
    }

    // phase 1: S = tril(Qp Kp^T), 128x128
    const int ti = tid >> 4, tj = tid & 15;
    {
        float acc[8][8];
        #pragma unroll
        for (int i = 0; i < 8; i++)
            #pragma unroll
            for (int j = 0; j < 8; j++) acc[i][j] = 0.f;
        #pragma unroll 16
        for (int k = 0; k < 64; k++) {
            float4 a0 = *(const float4*)&Qt[k*132 + ti*8];
            float4 a1 = *(const float4*)&Qt[k*132 + ti*8 + 4];
            float4 b0 = *(const float4*)&Kt[k*132 + tj*8];
            float4 b1 = *(const float4*)&Kt[k*132 + tj*8 + 4];
            float av[8] = {a0.x,a0.y,a0.z,a0.w,a1.x,a1.y,a1.z,a1.w};
            float bv[8] = {b0.x,b0.y,b0.z,b0.w,b1.x,b1.y,b1.z,b1.w};
            #pragma unroll
            for (int i = 0; i < 8; i++)
                #pragma unroll
                for (int j = 0; j < 8; j++)
                    acc[i][j] = fmaf(av[i], bv[j], acc[i][j]);
        }
        #pragma unroll
        for (int i = 0; i < 8; i++) {
            int row = ti*8 + i;
            #pragma unroll
            for (int j = 0; j < 8; j++) {
                int col = tj*8 + j;
                Ss[row*132 + col] = (col <= row) ? acc[i][j] : 0.f;
            }
        }
    }
    __syncthreads();

    // phase 2: num = S*V + Qp*KV, scale by dinv, store
    {
        float acc[8][4];
        #pragma unroll
        for (int i = 0; i < 8; i++)
            #pragma unroll
            for (int j = 0; j < 4; j++) acc[i][j] = 0.f;

        #pragma unroll 8
        for (int k = 0; k < 128; k++) {
            float4 bv = *(const float4*)&Vs[k*64 + tj*4];
            #pragma unroll
            for (int i = 0; i < 8; i++) {
                float a = Ss[(ti*8 + i)*132 + k];
                acc[i][0] = fmaf(a, bv.x, acc[i][0]);
                acc[i][1] = fmaf(a, bv.y, acc[i][1]);
                acc[i][2] = fmaf(a, bv.z, acc[i][2]);
                acc[i][3] = fmaf(a, bv.w, acc[i][3]);
            }
        }
        #pragma unroll 8
        for (int k = 0; k < 64; k++) {
            float4 bv = *(const float4*)&KVs[k*64 + tj*4];
            #pragma unroll
            for (int i = 0; i < 8; i++) {
                float a = Qt[k*132 + ti*8 + i];
                acc[i][0] = fmaf(a, bv.x, acc[i][0]);
                acc[i][1] = fmaf(a, bv.y, acc[i][1]);
                acc[i][2] = fmaf(a, bv.z, acc[i][2]);
                acc[i][3] = fmaf(a, bv.w, acc[i][3]);
            }
        }
        #pragma unroll
        for (int i = 0; i < 8; i++) {
            int t = ti*8 + i;
            float dv = dinv[t];
            float4 o = {acc[i][0]*dv, acc[i][1]*dv, acc[i][2]*dv, acc[i][3]*dv};
            *(float4*)&g_attn[(t0 + t)*(NHEAD*HDIM) + h*64 + tj*4] = o;
        }
    }
}

// ---------------- launch ------------------------------------------------------
extern "C" void kernel_launch(void* const* d_in, const int* in_sizes, int n_in,
                              void* d_out, int out_size)
{
    const float* hidden = (const float*)d_in[0];
    const float* cosg   = (const float*)d_in[1];
    const float* sing   = (const float*)d_in[2];
    const float* W_qkv  = (const float*)d_in[3];
    const float* W_o    = (const float*)d_in[4];
    const float* proj   = (const float*)d_in[5];
    float* out = (float*)d_out;

    static bool attr_done = false;
    if (!attr_done) {
        cudaFuncSetAttribute(chunkkv_kernel,
            cudaFuncAttributeMaxDynamicSharedMemorySize, 65536);
        cudaFuncSetAttribute(stage_d_kernel,
            cudaFuncAttributeMaxDynamicSharedMemorySize, SD_BYTES);
        attr_done = true;
    }

    float* qkv  = nullptr; cudaGetSymbolAddress((void**)&qkv,  g_qkv);
    float* attn = nullptr; cudaGetSymbolAddress((void**)&attn, g_attn);

    // 1. qkv = hidden @ W_qkv^T
    gemm_nt_kernel<<<dim3(QKVD/128, MROWS/128), 256>>>(hidden, W_qkv, qkv,
                                                       MROWS, QKVD, 1024);
    // 2. rope + feature projection
    ropeproj_kernel<<<(MROWS*24)/64, 256>>>(cosg, sing, proj);
    // 3. z scan
    zscan_kernel<<<Bv*NKVH, 128>>>();
    // 4. per-chunk KV
    chunkkv_kernel<<<dim3(NCHUNK, Bv*NKVH), 256, 65536>>>();
    // 5. exclusive chunk prefix
    kvprefix_kernel<<<Bv*NKVH, 256>>>();
    // 6. causal combine
    stage_d_kernel<<<dim3(NCHUNK, NHEAD, Bv), 256, SD_BYTES>>>();
    // 7. out = attn @ W_o^T
    gemm_nt_kernel<<<dim3(1024/128, MROWS/128), 256>>>(attn, W_o, out,
                                                       MROWS, 1024, 1024);
}

// round 4
// speedup vs baseline: 1.1198x; 1.1198x over previous
#include <cuda_runtime.h>
#include <cuda_bf16.h>
#include <cstdint>

#define Bv      2
#define Sv      4096
#define QKVD    2048
#define NHEAD   16
#define NKVH    8
#define HDIM    64
#define NFEAT   64
#define CHUNK   128
#define NCHUNK  32
#define MROWS   (Bv*Sv)

// ---------------- scratch (device globals; no allocs allowed) ----------------
__device__ float g_qkv [(size_t)MROWS*QKVD];
__device__ float g_qp  [(size_t)MROWS*NHEAD*NFEAT];
__device__ float g_kp  [(size_t)MROWS*NKVH*NFEAT];
__device__ float g_z   [(size_t)Bv*NKVH*Sv];
__device__ float g_kvc [(size_t)Bv*NKVH*NCHUNK*NFEAT*HDIM];
__device__ float g_attn[(size_t)MROWS*(NHEAD*HDIM)];

__device__ __nv_bfloat16 g_ahi [(size_t)MROWS*1024];
__device__ __nv_bfloat16 g_alo [(size_t)MROWS*1024];
__device__ __nv_bfloat16 g_w1hi[(size_t)2048*1024];
__device__ __nv_bfloat16 g_w1lo[(size_t)2048*1024];
__device__ __nv_bfloat16 g_w2hi[(size_t)1024*1024];
__device__ __nv_bfloat16 g_w2lo[(size_t)1024*1024];

// ---------------- PTX helpers -------------------------------------------------
__device__ __forceinline__ uint32_t smem_u32(const void* p) {
    uint32_t a;
    asm("{ .reg .u64 t; cvta.to.shared.u64 t, %1; cvt.u32.u64 %0, t; }" : "=r"(a) : "l"(p));
    return a;
}
__device__ __forceinline__ void ldsm_x4(uint32_t& r0, uint32_t& r1,
                                        uint32_t& r2, uint32_t& r3, uint32_t a) {
    asm volatile("ldmatrix.sync.aligned.m8n8.x4.shared.b16 {%0,%1,%2,%3}, [%4];"
                 : "=r"(r0), "=r"(r1), "=r"(r2), "=r"(r3) : "r"(a));
}
__device__ __forceinline__ void ldsm_x2(uint32_t& r0, uint32_t& r1, uint32_t a) {
    asm volatile("ldmatrix.sync.aligned.m8n8.x2.shared.b16 {%0,%1}, [%2];"
                 : "=r"(r0), "=r"(r1) : "r"(a));
}
__device__ __forceinline__ void mma_bf16(float* d,
    uint32_t a0, uint32_t a1, uint32_t a2, uint32_t a3, uint32_t b0, uint32_t b1) {
    asm volatile(
        "mma.sync.aligned.m16n8k16.row.col.f32.bf16.bf16.f32 "
        "{%0,%1,%2,%3}, {%4,%5,%6,%7}, {%8,%9}, {%0,%1,%2,%3};"
        : "+f"(d[0]), "+f"(d[1]), "+f"(d[2]), "+f"(d[3])
        : "r"(a0), "r"(a1), "r"(a2), "r"(a3), "r"(b0), "r"(b1));
}

// ---------------- fp32 -> bf16 hi/lo split ------------------------------------
__global__ void __launch_bounds__(256) cvt_split_kernel(
    const float* __restrict__ src,
    __nv_bfloat16* __restrict__ hi, __nv_bfloat16* __restrict__ lo, int n)
{
    int i = (blockIdx.x * 256 + threadIdx.x) * 4;
    if (i >= n) return;
    float4 v = *(const float4*)(src + i);
    __nv_bfloat16 h0 = __float2bfloat16(v.x);
    __nv_bfloat16 h1 = __float2bfloat16(v.y);
    __nv_bfloat16 h2 = __float2bfloat16(v.z);
    __nv_bfloat16 h3 = __float2bfloat16(v.w);
    __nv_bfloat16 l0 = __float2bfloat16(v.x - __bfloat162float(h0));
    __nv_bfloat16 l1 = __float2bfloat16(v.y - __bfloat162float(h1));
    __nv_bfloat16 l2 = __float2bfloat16(v.z - __bfloat162float(h2));
    __nv_bfloat16 l3 = __float2bfloat16(v.w - __bfloat162float(h3));
    __nv_bfloat162* hp = (__nv_bfloat162*)(hi + i);
    __nv_bfloat162* lp = (__nv_bfloat162*)(lo + i);
    hp[0] = __nv_bfloat162(h0, h1); hp[1] = __nv_bfloat162(h2, h3);
    lp[0] = __nv_bfloat162(l0, l1); lp[1] = __nv_bfloat162(l2, l3);
}

// ---------------- mma.sync GEMM: C[M,N] = A[M,K] * B[N,K]^T -------------------
// bf16 split: C = Ahi*Bhi + Ahi*Blo + Alo*Bhi, fp32 accumulators.
// 128x128 tile, 8 warps (2x4, 64x32 each), K-chunk 32, double buffered.
#define GM_PAD  40
#define GM_BUF  (128*GM_PAD)
#define GM_SMEM (2*4*GM_BUF*2)          /* 81920 bytes */

__global__ void __launch_bounds__(256) gemm_mma_kernel(
    const __nv_bfloat16* __restrict__ Ahi, const __nv_bfloat16* __restrict__ Alo,
    const __nv_bfloat16* __restrict__ Bhi, const __nv_bfloat16* __restrict__ Blo,
    float* __restrict__ C, int N, int K)
{
    extern __shared__ __nv_bfloat16 smh[];   // [buf][arr][128][GM_PAD]
    const int tid = threadIdx.x;
    const int m0 = blockIdx.y * 128, n0 = blockIdx.x * 128;
    const int row = tid >> 1, off = (tid & 1) * 16;

    const __nv_bfloat16* gp0 = Ahi + (size_t)(m0 + row) * K + off;
    const __nv_bfloat16* gp1 = Alo + (size_t)(m0 + row) * K + off;
    const __nv_bfloat16* gp2 = Bhi + (size_t)(n0 + row) * K + off;
    const __nv_bfloat16* gp3 = Blo + (size_t)(n0 + row) * K + off;

    const int wid = tid >> 5, lane = tid & 31;
    const int wm = wid >> 2, wn = wid & 3;
    const int l16 = lane & 15;

    float acc[4][4][4];
    #pragma unroll
    for (int mi = 0; mi < 4; mi++)
        #pragma unroll
        for (int ni = 0; ni < 4; ni++)
            #pragma unroll
            for (int r = 0; r < 4; r++) acc[mi][ni][r] = 0.f;

    const int sto = row * GM_PAD + off;
    uint4 ld[4][2];

    // prologue: chunk 0
    ld[0][0] = *(const uint4*)gp0;       ld[0][1] = *(const uint4*)(gp0 + 8);
    ld[1][0] = *(const uint4*)gp1;       ld[1][1] = *(const uint4*)(gp1 + 8);
    ld[2][0] = *(const uint4*)gp2;       ld[2][1] = *(const uint4*)(gp2 + 8);
    ld[3][0] = *(const uint4*)gp3;       ld[3][1] = *(const uint4*)(gp3 + 8);
    #pragma unroll
    for (int arr = 0; arr < 4; arr++) {
        *(uint4*)&smh[arr*GM_BUF + sto]     = ld[arr][0];
        *(uint4*)&smh[arr*GM_BUF + sto + 8] = ld[arr][1];
    }
    __syncthreads();

    const int NKT = K >> 5;
    for (int kt = 0; kt < NKT; kt++) {
        const int b = kt & 1;
        if (kt + 1 < NKT) {
            const int kb = (kt + 1) << 5;
            ld[0][0] = *(const uint4*)(gp0 + kb); ld[0][1] = *(const uint4*)(gp0 + kb + 8);
            ld[1][0] = *(const uint4*)(gp1 + kb); ld[1][1] = *(const uint4*)(gp1 + kb + 8);
            ld[2][0] = *(const uint4*)(gp2 + kb); ld[2][1] = *(const uint4*)(gp2 + kb + 8);
            ld[3][0] = *(const uint4*)(gp3 + kb); ld[3][1] = *(const uint4*)(gp3 + kb + 8);
        }

        const __nv_bfloat16* sAh = smh + b*(4*GM_BUF);
        const __nv_bfloat16* sAl = sAh + GM_BUF;
        const __nv_bfloat16* sBh = sAl + GM_BUF;
        const __nv_bfloat16* sBl = sBh + GM_BUF;

        #pragma unroll
        for (int k16 = 0; k16 < 32; k16 += 16) {
            uint32_t ah[4][4], al[4][4];
            #pragma unroll
            for (int mi = 0; mi < 4; mi++) {
                int roff = (wm*64 + mi*16 + l16) * GM_PAD + k16 + (lane >> 4) * 8;
                ldsm_x4(ah[mi][0], ah[mi][1], ah[mi][2], ah[mi][3], smem_u32(sAh + roff));
                ldsm_x4(al[mi][0], al[mi][1], al[mi][2], al[mi][3], smem_u32(sAl + roff));
            }
            #pragma unroll
            for (int ni = 0; ni < 4; ni++) {
                int boff = (wn*32 + ni*8 + (l16 & 7)) * GM_PAD + k16 + ((l16 >> 3) & 1) * 8;
                uint32_t bh0, bh1, bl0, bl1;
                ldsm_x2(bh0, bh1, smem_u32(sBh + boff));
                ldsm_x2(bl0, bl1, smem_u32(sBl + boff));
                #pragma unroll
                for (int mi = 0; mi < 4; mi++) {
                    mma_bf16(acc[mi][ni], ah[mi][0], ah[mi][1], ah[mi][2], ah[mi][3], bh0, bh1);
                    mma_bf16(acc[mi][ni], ah[mi][0], ah[mi][1], ah[mi][2], ah[mi][3], bl0, bl1);
                    mma_bf16(acc[mi][ni], al[mi][0], al[mi][1], al[mi][2], al[mi][3], bh0, bh1);
                }
            }
        }

        if (kt + 1 < NKT) {
            __nv_bfloat16* dst = smh + (b ^ 1)*(4*GM_BUF);
            #pragma unroll
            for (int arr = 0; arr < 4; arr++) {
                *(uint4*)&dst[arr*GM_BUF + sto]     = ld[arr][0];
                *(uint4*)&dst[arr*GM_BUF + sto + 8] = ld[arr][1];
            }
        }
        __syncthreads();
    }

    const int g = lane >> 2, tg = lane & 3;
    #pragma unroll
    for (int mi = 0; mi < 4; mi++) {
        #pragma unroll
        for (int ni = 0; ni < 4; ni++) {
            int r0 = m0 + wm*64 + mi*16 + g;
            int c0 = n0 + wn*32 + ni*8 + tg*2;
            float2 lo = {acc[mi][ni][0], acc[mi][ni][1]};
            float2 hi = {acc[mi][ni][2], acc[mi][ni][3]};
            *(float2*)&C[(size_t)r0 * N + c0]       = lo;
            *(float2*)&C[(size_t)(r0 + 8) * N + c0] = hi;
        }
    }
}

// ---------------- RoPE + relu feature projection (q and k heads) -------------
__global__ void __launch_bounds__(256) ropeproj_kernel(
    const float* __restrict__ cosg, const float* __restrict__ sing,
    const float* __restrict__ proj)
{
    __shared__ float dat[64*68];
    __shared__ float pj [64*68];
    const int tid = threadIdx.x;
    const int rbase = blockIdx.x * 64;

    #pragma unroll
    for (int j = 0; j < 16; j++) {
        int i = tid + j*256;
        int f = i >> 6, d = i & 63;
        pj[d*68 + f] = proj[i];
    }
    #pragma unroll
    for (int j = 0; j < 16; j++) {
        int e = tid + j*256;
        int r = e >> 6, d = e & 63;
        int rho = rbase + r;
        int bs  = rho / 24;
        int h   = rho - bs*24;
        int s   = bs & (Sv-1);
        size_t base = (size_t)bs*QKVD + h*64;
        float val  = g_qkv[base + d];
        int   pd   = (d < 32) ? d + 32 : d - 32;
        float part = g_qkv[base + pd];
        float rot  = (d < 32) ? -part : part;
        dat[d*68 + r] = fmaf(val, cosg[s*64 + d], rot * sing[s*64 + d]);
    }
    __syncthreads();

    const int rq = tid >> 4, fq = tid & 15;
    float acc[4][4];
    #pragma unroll
    for (int i = 0; i < 4; i++)
        #pragma unroll
        for (int j = 0; j < 4; j++) acc[i][j] = 0.f;

    #pragma unroll
    for (int k = 0; k < 64; k++) {
        float4 a = *(const float4*)&dat[k*68 + rq*4];
        float4 b = *(const float4*)&pj [k*68 + fq*4];
        float av[4] = {a.x,a.y,a.z,a.w};
        float bv[4] = {b.x,b.y,b.z,b.w};
        #pragma unroll
        for (int i = 0; i < 4; i++)
            #pragma unroll
            for (int j = 0; j < 4; j++)
                acc[i][j] = fmaf(av[i], bv[j], acc[i][j]);
    }

    const float ratio = (float)(0.125 * (0.125 + 1e-4));
    #pragma unroll
    for (int i = 0; i < 4; i++) {
        int rho = rbase + rq*4 + i;
        int bs  = rho / 24;
        int h   = rho - bs*24;
        float4 o;
        o.x = fmaxf(acc[i][0]*ratio, 0.f);
        o.y = fmaxf(acc[i][1]*ratio, 0.f);
        o.z = fmaxf(acc[i][2]*ratio, 0.f);
        o.w = fmaxf(acc[i][3]*ratio, 0.f);
        if (h < NHEAD) {
            o.x += 1e-4f; o.y += 1e-4f; o.z += 1e-4f; o.w += 1e-4f;
            *(float4*)&g_qp[((size_t)bs*NHEAD + h)*NFEAT + fq*4] = o;
        } else {
            *(float4*)&g_kp[((size_t)bs*NKVH + (h - NHEAD))*NFEAT + fq*4] = o;
        }
    }
}

// ---------------- inclusive prefix of rowsum(kp) over t, per (b,kvh) ---------
__global__ void __launch_bounds__(128) zscan_kernel()
{
    const int bkv = blockIdx.x;
    const int b   = bkv >> 3, kvh = bkv & 7;
    const int tid = threadIdx.x;
    const int lane = tid & 31, warp = tid >> 5;
    __shared__ float wsum[4];
    float carry = 0.f;

    for (int tile = 0; tile < 32; tile++) {
        int t = tile*128 + tid;
        const float* row = g_kp + (((size_t)(b*Sv + t))*NKVH + kvh)*NFEAT;
        float s = 0.f;
        #pragma unroll
        for (int f = 0; f < 64; f += 4) {
            float4 v = *(const float4*)(row + f);
            s += (v.x + v.y) + (v.z + v.w);
        }
        float x = s;
        #pragma unroll
        for (int o = 1; o < 32; o <<= 1) {
            float n = __shfl_up_sync(0xffffffffu, x, o);
            if (lane >= o) x += n;
        }
        if (lane == 31) wsum[warp] = x;
        __syncthreads();
        float off = carry;
        for (int w2 = 0; w2 < warp; w2++) off += wsum[w2];
        g_z[(size_t)bkv*Sv + t] = off + x;
        carry += wsum[0] + wsum[1] + wsum[2] + wsum[3];
        __syncthreads();
    }
}

// ---------------- per-chunk KV = Kp^T V (64x64) ------------------------------
__global__ void __launch_bounds__(256) chunkkv_kernel()
{
    extern __shared__ float cs[];
    float* Ks = cs;
    float* Vs = cs + 8192;
    const int c   = blockIdx.x;
    const int bkv = blockIdx.y;
    const int b   = bkv >> 3, kvh = bkv & 7;
    const int tid = threadIdx.x;

    #pragma unroll
    for (int j = 0; j < 32; j++) {
        int e = tid + j*256;
        int t = e >> 6, f = e & 63;
        size_t bs = (size_t)(b*Sv + c*CHUNK + t);
        Ks[e] = g_kp[(bs*NKVH + kvh)*NFEAT + f];
        Vs[e] = g_qkv[bs*QKVD + 1536 + kvh*64 + f];
    }
    __syncthreads();

    const int fq = tid >> 4, dq = tid & 15;
    float acc[4][4];
    #pragma unroll
    for (int i = 0; i < 4; i++)
        #pragma unroll
        for (int j = 0; j < 4; j++) acc[i][j] = 0.f;

    #pragma unroll 8
    for (int t = 0; t < 128; t++) {
        float4 a = *(const float4*)&Ks[t*64 + fq*4];
        float4 v = *(const float4*)&Vs[t*64 + dq*4];
        float av[4] = {a.x,a.y,a.z,a.w};
        #pragma unroll
        for (int i = 0; i < 4; i++) {
            acc[i][0] = fmaf(av[i], v.x, acc[i][0]);
            acc[i][1] = fmaf(av[i], v.y, acc[i][1]);
            acc[i][2] = fmaf(av[i], v.z, acc[i][2]);
            acc[i][3] = fmaf(av[i], v.w, acc[i][3]);
        }
    }
    size_t base = ((size_t)bkv*NCHUNK + c)*4096;
    #pragma unroll
    for (int i = 0; i < 4; i++) {
        float4 o = {acc[i][0], acc[i][1], acc[i][2], acc[i][3]};
        *(float4*)&g_kvc[base + (size_t)(fq*4 + i)*64 + dq*4] = o;
    }
}

// ---------------- exclusive chunk-prefix of KV, in place ---------------------
__global__ void __launch_bounds__(256) kvprefix_kernel()
{
    const int bkv = blockIdx.x;
    const int tid = threadIdx.x;
    float acc[16];
    #pragma unroll
    for (int j = 0; j < 16; j++) acc[j] = 0.f;
    for (int c = 0; c < NCHUNK; c++) {
        size_t base = ((size_t)bkv*NCHUNK + c)*4096;
        #pragma unroll
        for (int j = 0; j < 16; j++) {
            size_t idx = base + tid + j*256;
            float cur = g_kvc[idx];
            g_kvc[idx] = acc[j];
            acc[j] += cur;
        }
    }
}

// ---------------- stage D: intra-chunk causal + prefix term ------------------
#define SD_FLOATS (64*132 + 64*132 + 128*132 + 128*64 + 64*64 + 128)
#define SD_BYTES  (SD_FLOATS*4)

__global__ void __launch_bounds__(256) stage_d_kernel()
{
    extern __shared__ float sm[];
    float* Qt   = sm;
    float* Kt   = Qt  + 64*132;
    float* Ss   = Kt  + 64*132;
    float* Vs   = Ss  + 128*132;
    float* KVs  = Vs  + 128*64;
    float* dinv = KVs + 64*64;

    const int c   = blockIdx.x;
    const int h   = blockIdx.y;
    const int b   = blockIdx.z;
    const int kvh = h >> 1;
    const int tid = threadIdx.x;
    const size_t t0 = (size_t)b*Sv + c*CHUNK;

    #pragma unroll
    for (int j = 0; j < 32; j++) {
        int e = tid + j*256;
        int t = e >> 6, f = e & 63;
        Qt[f*132 + t] = g_qp[((t0 + t)*NHEAD + h)*NFEAT + f];
        Kt[f*132 + t] = g_kp[((t0 + t)*NKVH + kvh)*NFEAT + f];
        Vs[e]         = g_qkv[(t0 + t)*QKVD + 1536 + kvh*64 + f];
    }
    #pragma unroll
    for (int j = 0; j < 16; j++) {
        int e = tid + j*256;
        KVs[e] = g_kvc[(((size_t)(b*NKVH + kvh))*NCHUNK + c)*4096 + e];
    }
    __syncthreads();

    if (tid < 128) {
        float s = 0.f;
        #pragma unroll
        for (int f = 0; f < 64; f++) s += Qt[f*132 + tid];
        float z = g_z[((size_t)(b*NKVH + kvh))*Sv + c*CHUNK + tid];
        dinv[tid] = 1.0f / (s*z + 1e-6f);
    }

    const int ti = tid >> 4, tj = tid & 15;
    {
        float acc[8][8];
        #pragma unroll
        for (int i = 0; i < 8; i++)
            #pragma unroll
            for (int j = 0; j < 8; j++) acc[i][j] = 0.f;
        #pragma unroll 16
        for (int k = 0; k < 64; k++) {
            float4 a0 = *(const float4*)&Qt[k*132 + ti*8];
            float4 a1 = *(const float4*)&Qt[k*132 + ti*8 + 4];
            float4 b0 = *(const float4*)&Kt[k*132 + tj*8];
            float4 b1 = *(const float4*)&Kt[k*132 + tj*8 + 4];
            float av[8] = {a0.x,a0.y,a0.z,a0.w,a1.x,a1.y,a1.z,a1.w};
            float bv[8] = {b0.x,b0.y,b0.z,b0.w,b1.x,b1.y,b1.z,b1.w};
            #pragma unroll
            for (int i = 0; i < 8; i++)
                #pragma unroll
                for (int j = 0; j < 8; j++)
                    acc[i][j] = fmaf(av[i], bv[j], acc[i][j]);
        }
        #pragma unroll
        for (int i = 0; i < 8; i++) {
            int row = ti*8 + i;
            #pragma unroll
            for (int j = 0; j < 8; j++) {
                int col = tj*8 + j;
                Ss[row*132 + col] = (col <= row) ? acc[i][j] : 0.f;
            }
        }
    }
    __syncthreads();

    {
        float acc[8][4];
        #pragma unroll
        for (int i = 0; i < 8; i++)
            #pragma unroll
            for (int j = 0; j < 4; j++) acc[i][j] = 0.f;

        #pragma unroll 8
        for (int k = 0; k < 128; k++) {
            float4 bv = *(const float4*)&Vs[k*64 + tj*4];
            #pragma unroll
            for (int i = 0; i < 8; i++) {
                float a = Ss[(ti*8 + i)*132 + k];
                acc[i][0] = fmaf(a, bv.x, acc[i][0]);
                acc[i][1] = fmaf(a, bv.y, acc[i][1]);
                acc[i][2] = fmaf(a, bv.z, acc[i][2]);
                acc[i][3] = fmaf(a, bv.w, acc[i][3]);
            }
        }
        #pragma unroll 8
        for (int k = 0; k < 64; k++) {
            float4 bv = *(const float4*)&KVs[k*64 + tj*4];
            #pragma unroll
            for (int i = 0; i < 8; i++) {
                float a = Qt[k*132 + ti*8 + i];
                acc[i][0] = fmaf(a, bv.x, acc[i][0]);
                acc[i][1] = fmaf(a, bv.y, acc[i][1]);
                acc[i][2] = fmaf(a, bv.z, acc[i][2]);
                acc[i][3] = fmaf(a, bv.w, acc[i][3]);
            }
        }
        #pragma unroll
        for (int i = 0; i < 8; i++) {
            int t = ti*8 + i;
            float dv = dinv[t];
            float4 o = {acc[i][0]*dv, acc[i][1]*dv, acc[i][2]*dv, acc[i][3]*dv};
            *(float4*)&g_attn[(t0 + t)*(NHEAD*HDIM) + h*64 + tj*4] = o;
        }
    }
}

// ---------------- launch ------------------------------------------------------
extern "C" void kernel_launch(void* const* d_in, const int* in_sizes, int n_in,
                              void* d_out, int out_size)
{
    const float* hidden = (const float*)d_in[0];
    const float* cosg   = (const float*)d_in[1];
    const float* sing   = (const float*)d_in[2];
    const float* W_qkv  = (const float*)d_in[3];
    const float* W_o    = (const float*)d_in[4];
    const float* proj   = (const float*)d_in[5];
    float* out = (float*)d_out;

    static bool attr_done = false;
    if (!attr_done) {
        cudaFuncSetAttribute(chunkkv_kernel,
            cudaFuncAttributeMaxDynamicSharedMemorySize, 65536);
        cudaFuncSetAttribute(stage_d_kernel,
            cudaFuncAttributeMaxDynamicSharedMemorySize, SD_BYTES);
        cudaFuncSetAttribute(gemm_mma_kernel,
            cudaFuncAttributeMaxDynamicSharedMemorySize, GM_SMEM);
        attr_done = true;
    }

    float* qkv  = nullptr; cudaGetSymbolAddress((void**)&qkv,  g_qkv);
    float* attn = nullptr; cudaGetSymbolAddress((void**)&attn, g_attn);
    __nv_bfloat16 *ahi, *alo, *w1hi, *w1lo, *w2hi, *w2lo;
    cudaGetSymbolAddress((void**)&ahi,  g_ahi);
    cudaGetSymbolAddress((void**)&alo,  g_alo);
    cudaGetSymbolAddress((void**)&w1hi, g_w1hi);
    cudaGetSymbolAddress((void**)&w1lo, g_w1lo);
    cudaGetSymbolAddress((void**)&w2hi, g_w2hi);
    cudaGetSymbolAddress((void**)&w2lo, g_w2lo);

    // 1. split-convert hidden + W_qkv, then QKV GEMM on tensor cores
    cvt_split_kernel<<<(MROWS*1024)/1024, 256>>>(hidden, ahi, alo, MROWS*1024);
    cvt_split_kernel<<<(2048*1024)/1024, 256>>>(W_qkv, w1hi, w1lo, 2048*1024);
    gemm_mma_kernel<<<dim3(QKVD/128, MROWS/128), 256, GM_SMEM>>>(
        ahi, alo, w1hi, w1lo, qkv, QKVD, 1024);

    // 2. rope + feature projection
    ropeproj_kernel<<<(MROWS*24)/64, 256>>>(cosg, sing, proj);
    // 3. z scan
    zscan_kernel<<<Bv*NKVH, 128>>>();
    // 4. per-chunk KV
    chunkkv_kernel<<<dim3(NCHUNK, Bv*NKVH), 256, 65536>>>();
    // 5. exclusive chunk prefix
    kvprefix_kernel<<<Bv*NKVH, 256>>>();
    // 6. causal combine
    stage_d_kernel<<<dim3(NCHUNK, NHEAD, Bv), 256, SD_BYTES>>>();

    // 7. split-convert attn + W_o, then output GEMM on tensor cores
    cvt_split_kernel<<<(MROWS*1024)/1024, 256>>>(attn, ahi, alo, MROWS*1024);
    cvt_split_kernel<<<(1024*1024)/1024, 256>>>(W_o, w2hi, w2lo, 1024*1024);
    gemm_mma_kernel<<<dim3(1024/128, MROWS/128), 256, GM_SMEM>>>(
        ahi, alo, w2hi, w2lo, out, 1024, 1024);
}

// round 5
// speedup vs baseline: 1.8681x; 1.6682x over previous
#include <cuda_runtime.h>
#include <cuda_bf16.h>
#include <cstdint>

#define Bv      2
#define Sv      4096
#define QKVD    2048
#define NHEAD   16
#define NKVH    8
#define HDIM    64
#define NFEAT   64
#define CHUNK   128
#define NCHUNK  32
#define MROWS   (Bv*Sv)

// ---------------- scratch (device globals; no allocs allowed) ----------------
__device__ float g_qkv [(size_t)MROWS*QKVD];
__device__ float g_qp  [(size_t)MROWS*NHEAD*NFEAT];
__device__ float g_kp  [(size_t)MROWS*NKVH*NFEAT];
__device__ float g_z   [(size_t)Bv*NKVH*Sv];
__device__ float g_kvc [(size_t)Bv*NKVH*NCHUNK*NFEAT*HDIM];

__device__ __nv_bfloat16 g_ahi [(size_t)MROWS*1024];
__device__ __nv_bfloat16 g_alo [(size_t)MROWS*1024];
__device__ __nv_bfloat16 g_w1hi[(size_t)2048*1024];
__device__ __nv_bfloat16 g_w1lo[(size_t)2048*1024];
__device__ __nv_bfloat16 g_w2hi[(size_t)1024*1024];
__device__ __nv_bfloat16 g_w2lo[(size_t)1024*1024];

// ---------------- PTX helpers -------------------------------------------------
__device__ __forceinline__ uint32_t smem_u32(const void* p) {
    uint32_t a;
    asm("{ .reg .u64 t; cvta.to.shared.u64 t, %1; cvt.u32.u64 %0, t; }" : "=r"(a) : "l"(p));
    return a;
}
__device__ __forceinline__ void ldsm_x4(uint32_t& r0, uint32_t& r1,
                                        uint32_t& r2, uint32_t& r3, uint32_t a) {
    asm volatile("ldmatrix.sync.aligned.m8n8.x4.shared.b16 {%0,%1,%2,%3}, [%4];"
                 : "=r"(r0), "=r"(r1), "=r"(r2), "=r"(r3) : "r"(a));
}
__device__ __forceinline__ void ldsm_x2(uint32_t& r0, uint32_t& r1, uint32_t a) {
    asm volatile("ldmatrix.sync.aligned.m8n8.x2.shared.b16 {%0,%1}, [%2];"
                 : "=r"(r0), "=r"(r1) : "r"(a));
}
__device__ __forceinline__ void ldsm_x2_t(uint32_t& r0, uint32_t& r1, uint32_t a) {
    asm volatile("ldmatrix.sync.aligned.m8n8.x2.trans.shared.b16 {%0,%1}, [%2];"
                 : "=r"(r0), "=r"(r1) : "r"(a));
}
__device__ __forceinline__ void mma_bf16(float* d,
    uint32_t a0, uint32_t a1, uint32_t a2, uint32_t a3, uint32_t b0, uint32_t b1) {
    asm volatile(
        "mma.sync.aligned.m16n8k16.row.col.f32.bf16.bf16.f32 "
        "{%0,%1,%2,%3}, {%4,%5,%6,%7}, {%8,%9}, {%0,%1,%2,%3};"
        : "+f"(d[0]), "+f"(d[1]), "+f"(d[2]), "+f"(d[3])
        : "r"(a0), "r"(a1), "r"(a2), "r"(a3), "r"(b0), "r"(b1));
}
__device__ __forceinline__ uint32_t pack2(float x, float y) {
    __nv_bfloat16 bx = __float2bfloat16(x), by = __float2bfloat16(y);
    return (uint32_t)__bfloat16_as_ushort(bx) |
           ((uint32_t)__bfloat16_as_ushort(by) << 16);
}

// ---------------- fp32 -> bf16 hi/lo split ------------------------------------
__global__ void __launch_bounds__(256) cvt_split_kernel(
    const float* __restrict__ src,
    __nv_bfloat16* __restrict__ hi, __nv_bfloat16* __restrict__ lo, int n)
{
    int i = (blockIdx.x * 256 + threadIdx.x) * 4;
    if (i >= n) return;
    float4 v = *(const float4*)(src + i);
    __nv_bfloat16 h0 = __float2bfloat16(v.x);
    __nv_bfloat16 h1 = __float2bfloat16(v.y);
    __nv_bfloat16 h2 = __float2bfloat16(v.z);
    __nv_bfloat16 h3 = __float2bfloat16(v.w);
    __nv_bfloat16 l0 = __float2bfloat16(v.x - __bfloat162float(h0));
    __nv_bfloat16 l1 = __float2bfloat16(v.y - __bfloat162float(h1));
    __nv_bfloat16 l2 = __float2bfloat16(v.z - __bfloat162float(h2));
    __nv_bfloat16 l3 = __float2bfloat16(v.w - __bfloat162float(h3));
    __nv_bfloat162* hp = (__nv_bfloat162*)(hi + i);
    __nv_bfloat162* lp = (__nv_bfloat162*)(lo + i);
    hp[0] = __nv_bfloat162(h0, h1); hp[1] = __nv_bfloat162(h2, h3);
    lp[0] = __nv_bfloat162(l0, l1); lp[1] = __nv_bfloat162(l2, l3);
}

// ---------------- mma.sync GEMM: C[M,N] = A[M,K] * B[N,K]^T -------------------
#define GM_PAD  40
#define GM_BUF  (128*GM_PAD)
#define GM_SMEM (2*4*GM_BUF*2)

__global__ void __launch_bounds__(256) gemm_mma_kernel(
    const __nv_bfloat16* __restrict__ Ahi, const __nv_bfloat16* __restrict__ Alo,
    const __nv_bfloat16* __restrict__ Bhi, const __nv_bfloat16* __restrict__ Blo,
    float* __restrict__ C, int N, int K)
{
    extern __shared__ __nv_bfloat16 smh[];
    const int tid = threadIdx.x;
    const int m0 = blockIdx.y * 128, n0 = blockIdx.x * 128;
    const int row = tid >> 1, off = (tid & 1) * 16;

    const __nv_bfloat16* gp0 = Ahi + (size_t)(m0 + row) * K + off;
    const __nv_bfloat16* gp1 = Alo + (size_t)(m0 + row) * K + off;
    const __nv_bfloat16* gp2 = Bhi + (size_t)(n0 + row) * K + off;
    const __nv_bfloat16* gp3 = Blo + (size_t)(n0 + row) * K + off;

    const int wid = tid >> 5, lane = tid & 31;
    const int wm = wid >> 2, wn = wid & 3;
    const int l16 = lane & 15;

    float acc[4][4][4];
    #pragma unroll
    for (int mi = 0; mi < 4; mi++)
        #pragma unroll
        for (int ni = 0; ni < 4; ni++)
            #pragma unroll
            for (int r = 0; r < 4; r++) acc[mi][ni][r] = 0.f;

    const int sto = row * GM_PAD + off;
    uint4 ld[4][2];

    ld[0][0] = *(const uint4*)gp0;       ld[0][1] = *(const uint4*)(gp0 + 8);
    ld[1][0] = *(const uint4*)gp1;       ld[1][1] = *(const uint4*)(gp1 + 8);
    ld[2][0] = *(const uint4*)gp2;       ld[2][1] = *(const uint4*)(gp2 + 8);
    ld[3][0] = *(const uint4*)gp3;       ld[3][1] = *(const uint4*)(gp3 + 8);
    #pragma unroll
    for (int arr = 0; arr < 4; arr++) {
        *(uint4*)&smh[arr*GM_BUF + sto]     = ld[arr][0];
        *(uint4*)&smh[arr*GM_BUF + sto + 8] = ld[arr][1];
    }
    __syncthreads();

    const int NKT = K >> 5;
    for (int kt = 0; kt < NKT; kt++) {
        const int b = kt & 1;
        if (kt + 1 < NKT) {
            const int kb = (kt + 1) << 5;
            ld[0][0] = *(const uint4*)(gp0 + kb); ld[0][1] = *(const uint4*)(gp0 + kb + 8);
            ld[1][0] = *(const uint4*)(gp1 + kb); ld[1][1] = *(const uint4*)(gp1 + kb + 8);
            ld[2][0] = *(const uint4*)(gp2 + kb); ld[2][1] = *(const uint4*)(gp2 + kb + 8);
            ld[3][0] = *(const uint4*)(gp3 + kb); ld[3][1] = *(const uint4*)(gp3 + kb + 8);
        }

        const __nv_bfloat16* sAh = smh + b*(4*GM_BUF);
        const __nv_bfloat16* sAl = sAh + GM_BUF;
        const __nv_bfloat16* sBh = sAl + GM_BUF;
        const __nv_bfloat16* sBl = sBh + GM_BUF;

        #pragma unroll
        for (int k16 = 0; k16 < 32; k16 += 16) {
            uint32_t ah[4][4], al[4][4];
            #pragma unroll
            for (int mi = 0; mi < 4; mi++) {
                int roff = (wm*64 + mi*16 + l16) * GM_PAD + k16 + (lane >> 4) * 8;
                ldsm_x4(ah[mi][0], ah[mi][1], ah[mi][2], ah[mi][3], smem_u32(sAh + roff));
                ldsm_x4(al[mi][0], al[mi][1], al[mi][2], al[mi][3], smem_u32(sAl + roff));
            }
            #pragma unroll
            for (int ni = 0; ni < 4; ni++) {
                int boff = (wn*32 + ni*8 + (l16 & 7)) * GM_PAD + k16 + ((l16 >> 3) & 1) * 8;
                uint32_t bh0, bh1, bl0, bl1;
                ldsm_x2(bh0, bh1, smem_u32(sBh + boff));
                ldsm_x2(bl0, bl1, smem_u32(sBl + boff));
                #pragma unroll
                for (int mi = 0; mi < 4; mi++) {
                    mma_bf16(acc[mi][ni], ah[mi][0], ah[mi][1], ah[mi][2], ah[mi][3], bh0, bh1);
                    mma_bf16(acc[mi][ni], ah[mi][0], ah[mi][1], ah[mi][2], ah[mi][3], bl0, bl1);
                    mma_bf16(acc[mi][ni], al[mi][0], al[mi][1], al[mi][2], al[mi][3], bh0, bh1);
                }
            }
        }

        if (kt + 1 < NKT) {
            __nv_bfloat16* dst = smh + (b ^ 1)*(4*GM_BUF);
            #pragma unroll
            for (int arr = 0; arr < 4; arr++) {
                *(uint4*)&dst[arr*GM_BUF + sto]     = ld[arr][0];
                *(uint4*)&dst[arr*GM_BUF + sto + 8] = ld[arr][1];
            }
        }
        __syncthreads();
    }

    const int g = lane >> 2, tg = lane & 3;
    #pragma unroll
    for (int mi = 0; mi < 4; mi++) {
        #pragma unroll
        for (int ni = 0; ni < 4; ni++) {
            int r0 = m0 + wm*64 + mi*16 + g;
            int c0 = n0 + wn*32 + ni*8 + tg*2;
            float2 lo = {acc[mi][ni][0], acc[mi][ni][1]};
            float2 hi = {acc[mi][ni][2], acc[mi][ni][3]};
            *(float2*)&C[(size_t)r0 * N + c0]       = lo;
            *(float2*)&C[(size_t)(r0 + 8) * N + c0] = hi;
        }
    }
}

// ---------------- RoPE + relu feature projection (128 thr, 8x4 tiles) --------
__global__ void __launch_bounds__(128) ropeproj_kernel(
    const float* __restrict__ cosg, const float* __restrict__ sing,
    const float* __restrict__ proj)
{
    __shared__ float dat[64*68];   // [d][r]
    __shared__ float pj [64*68];   // [d][f]
    const int tid = threadIdx.x;
    const int rbase = blockIdx.x * 64;

    #pragma unroll
    for (int j = 0; j < 32; j++) {
        int i = tid + j*128;
        int f = i >> 6, d = i & 63;
        pj[d*68 + f] = proj[i];
    }
    #pragma unroll
    for (int j = 0; j < 32; j++) {
        int e = tid + j*128;
        int r = e >> 6, d = e & 63;
        int rho = rbase + r;
        int bs  = rho / 24;
        int h   = rho - bs*24;
        int s   = bs & (Sv-1);
        size_t base = (size_t)bs*QKVD + h*64;
        float val  = g_qkv[base + d];
        int   pd   = (d < 32) ? d + 32 : d - 32;
        float part = g_qkv[base + pd];
        float rot  = (d < 32) ? -part : part;
        dat[d*68 + r] = fmaf(val, cosg[s*64 + d], rot * sing[s*64 + d]);
    }
    __syncthreads();

    const int rq = tid >> 4, fq = tid & 15;     // 8 row-groups x 16 col-groups
    float acc[8][4];
    #pragma unroll
    for (int i = 0; i < 8; i++)
        #pragma unroll
        for (int j = 0; j < 4; j++) acc[i][j] = 0.f;

    #pragma unroll
    for (int k = 0; k < 64; k++) {
        float4 a0 = *(const float4*)&dat[k*68 + rq*8];
        float4 a1 = *(const float4*)&dat[k*68 + rq*8 + 4];
        float4 bv = *(const float4*)&pj [k*68 + fq*4];
        float av[8] = {a0.x,a0.y,a0.z,a0.w,a1.x,a1.y,a1.z,a1.w};
        #pragma unroll
        for (int i = 0; i < 8; i++) {
            acc[i][0] = fmaf(av[i], bv.x, acc[i][0]);
            acc[i][1] = fmaf(av[i], bv.y, acc[i][1]);
            acc[i][2] = fmaf(av[i], bv.z, acc[i][2]);
            acc[i][3] = fmaf(av[i], bv.w, acc[i][3]);
        }
    }

    const float ratio = (float)(0.125 * (0.125 + 1e-4));
    #pragma unroll
    for (int i = 0; i < 8; i++) {
        int rho = rbase + rq*8 + i;
        int bs  = rho / 24;
        int h   = rho - bs*24;
        float4 o;
        o.x = fmaxf(acc[i][0]*ratio, 0.f);
        o.y = fmaxf(acc[i][1]*ratio, 0.f);
        o.z = fmaxf(acc[i][2]*ratio, 0.f);
        o.w = fmaxf(acc[i][3]*ratio, 0.f);
        if (h < NHEAD) {
            o.x += 1e-4f; o.y += 1e-4f; o.z += 1e-4f; o.w += 1e-4f;
            *(float4*)&g_qp[((size_t)bs*NHEAD + h)*NFEAT + fq*4] = o;
        } else {
            *(float4*)&g_kp[((size_t)bs*NKVH + (h - NHEAD))*NFEAT + fq*4] = o;
        }
    }
}

// ---------------- kp row sums (parallel) --------------------------------------
__global__ void __launch_bounds__(256) kpsum_kernel()
{
    int r = blockIdx.x * 256 + threadIdx.x;     // (b*Sv+t)*8 + kvh
    int bs = r >> 3, kvh = r & 7;
    int b = bs >> 12, t = bs & 4095;
    const float* row = g_kp + (size_t)r * 64;
    float s = 0.f;
    #pragma unroll
    for (int f = 0; f < 64; f += 4) {
        float4 v = *(const float4*)(row + f);
        s += (v.x + v.y) + (v.z + v.w);
    }
    g_z[((size_t)(b*8 + kvh))*Sv + t] = s;
}

// ---------------- inclusive scan of g_z per (b,kvh), in place -----------------
__global__ void __launch_bounds__(256) zscan_kernel()
{
    const int bkv = blockIdx.x;
    const int tid = threadIdx.x;
    const int lane = tid & 31, warp = tid >> 5;
    __shared__ float wsum[8];
    float carry = 0.f;

    for (int tile = 0; tile < 16; tile++) {
        int t = tile*256 + tid;
        float x = g_z[(size_t)bkv*Sv + t];
        #pragma unroll
        for (int o = 1; o < 32; o <<= 1) {
            float n = __shfl_up_sync(0xffffffffu, x, o);
            if (lane >= o) x += n;
        }
        if (lane == 31) wsum[warp] = x;
        __syncthreads();
        float off = carry;
        for (int w2 = 0; w2 < warp; w2++) off += wsum[w2];
        g_z[(size_t)bkv*Sv + t] = off + x;
        float tot = 0.f;
        #pragma unroll
        for (int w2 = 0; w2 < 8; w2++) tot += wsum[w2];
        carry += tot;
        __syncthreads();
    }
}

// ---------------- per-chunk KV = Kp^T V (64x64) ------------------------------
__global__ void __launch_bounds__(256) chunkkv_kernel()
{
    extern __shared__ float cs[];
    float* Ks = cs;
    float* Vs = cs + 8192;
    const int c   = blockIdx.x;
    const int bkv = blockIdx.y;
    const int b   = bkv >> 3, kvh = bkv & 7;
    const int tid = threadIdx.x;

    #pragma unroll
    for (int j = 0; j < 32; j++) {
        int e = tid + j*256;
        int t = e >> 6, f = e & 63;
        size_t bs = (size_t)(b*Sv + c*CHUNK + t);
        Ks[e] = g_kp[(bs*NKVH + kvh)*NFEAT + f];
        Vs[e] = g_qkv[bs*QKVD + 1536 + kvh*64 + f];
    }
    __syncthreads();

    const int fq = tid >> 4, dq = tid & 15;
    float acc[4][4];
    #pragma unroll
    for (int i = 0; i < 4; i++)
        #pragma unroll
        for (int j = 0; j < 4; j++) acc[i][j] = 0.f;

    #pragma unroll 8
    for (int t = 0; t < 128; t++) {
        float4 a = *(const float4*)&Ks[t*64 + fq*4];
        float4 v = *(const float4*)&Vs[t*64 + dq*4];
        float av[4] = {a.x,a.y,a.z,a.w};
        #pragma unroll
        for (int i = 0; i < 4; i++) {
            acc[i][0] = fmaf(av[i], v.x, acc[i][0]);
            acc[i][1] = fmaf(av[i], v.y, acc[i][1]);
            acc[i][2] = fmaf(av[i], v.z, acc[i][2]);
            acc[i][3] = fmaf(av[i], v.w, acc[i][3]);
        }
    }
    size_t base = ((size_t)bkv*NCHUNK + c)*4096;
    #pragma unroll
    for (int i = 0; i < 4; i++) {
        float4 o = {acc[i][0], acc[i][1], acc[i][2], acc[i][3]};
        *(float4*)&g_kvc[base + (size_t)(fq*4 + i)*64 + dq*4] = o;
    }
}

// ---------------- exclusive chunk-prefix of KV, in place ---------------------
__global__ void __launch_bounds__(256) kvprefix_kernel()
{
    const int bkv = blockIdx.x;
    const int tid = threadIdx.x;
    float acc[16];
    #pragma unroll
    for (int j = 0; j < 16; j++) acc[j] = 0.f;
    for (int c = 0; c < NCHUNK; c++) {
        size_t base = ((size_t)bkv*NCHUNK + c)*4096;
        #pragma unroll
        for (int j = 0; j < 16; j++) {
            size_t idx = base + tid + j*256;
            float cur = g_kvc[idx];
            g_kvc[idx] = acc[j];
            acc[j] += cur;
        }
    }
}

// ---------------- stage D: mma.sync split-bf16 causal combine ----------------
// smem (halves): sQ 128x72 hi/lo, sK 128x72 hi/lo, sV 128x72 hi/lo,
//                sC 64x72 hi/lo, sS 128x136 hi/lo, dinv 128 floats
#define SD_QP  72
#define SD_SP  136
#define SD_BYTES (99328*2 + 512)

__global__ void __launch_bounds__(256) stage_d_kernel()
{
    extern __shared__ __nv_bfloat16 sh[];
    __nv_bfloat16* sQh = sh;
    __nv_bfloat16* sQl = sh + 9216;
    __nv_bfloat16* sKh = sh + 18432;
    __nv_bfloat16* sKl = sh + 27648;
    __nv_bfloat16* sVh = sh + 36864;
    __nv_bfloat16* sVl = sh + 46080;
    __nv_bfloat16* sCh = sh + 55296;
    __nv_bfloat16* sCl = sh + 59904;
    __nv_bfloat16* sSh = sh + 64512;
    __nv_bfloat16* sSl = sh + 81920;
    float* dinv = (float*)(sh + 99328);

    const int c   = blockIdx.x;
    const int h   = blockIdx.y;
    const int b   = blockIdx.z;
    const int kvh = h >> 1;
    const int tid = threadIdx.x;
    const size_t t0 = (size_t)b*Sv + c*CHUNK;

    // load + split to bf16 hi/lo
    #pragma unroll
    for (int j = 0; j < 32; j++) {
        int e = tid + j*256;
        int t = e >> 6, f = e & 63;
        float q = g_qp[((t0 + t)*NHEAD + h)*NFEAT + f];
        float k = g_kp[((t0 + t)*NKVH + kvh)*NFEAT + f];
        float v = g_qkv[(t0 + t)*QKVD + 1536 + kvh*64 + f];
        __nv_bfloat16 qh = __float2bfloat16(q);
        __nv_bfloat16 kh = __float2bfloat16(k);
        __nv_bfloat16 vh = __float2bfloat16(v);
        sQh[t*SD_QP + f] = qh; sQl[t*SD_QP + f] = __float2bfloat16(q - __bfloat162float(qh));
        sKh[t*SD_QP + f] = kh; sKl[t*SD_QP + f] = __float2bfloat16(k - __bfloat162float(kh));
        sVh[t*SD_QP + f] = vh; sVl[t*SD_QP + f] = __float2bfloat16(v - __bfloat162float(vh));
    }
    #pragma unroll
    for (int j = 0; j < 16; j++) {
        int e = tid + j*256;
        int f = e >> 6, d = e & 63;
        float kv = g_kvc[(((size_t)(b*NKVH + kvh))*NCHUNK + c)*4096 + e];
        __nv_bfloat16 hh = __float2bfloat16(kv);
        sCh[f*SD_QP + d] = hh;
        sCl[f*SD_QP + d] = __float2bfloat16(kv - __bfloat162float(hh));
    }
    __syncthreads();

    if (tid < 128) {
        float s = 0.f;
        #pragma unroll
        for (int f = 0; f < 64; f++)
            s += __bfloat162float(sQh[tid*SD_QP + f]) + __bfloat162float(sQl[tid*SD_QP + f]);
        float z = g_z[((size_t)(b*NKVH + kvh))*Sv + c*CHUNK + tid];
        dinv[tid] = 1.0f / (s*z + 1e-6f);
    }
    __syncthreads();

    const int wid = tid >> 5, lane = tid & 31;
    const int l16 = lane & 15, g = lane >> 2, tg = lane & 3;
    const int mrow = wid * 16;
    const int ahalf = (lane >> 4) * 8;

    // phase 1: S = Qp Kp^T (128-wide per warp's 16 rows), 3-pass split
    {
        float accS[16][4];
        #pragma unroll
        for (int nt = 0; nt < 16; nt++)
            #pragma unroll
            for (int r = 0; r < 4; r++) accS[nt][r] = 0.f;

        #pragma unroll
        for (int k16 = 0; k16 < 64; k16 += 16) {
            int ro = (mrow + l16)*SD_QP + k16 + ahalf;
            uint32_t ah0,ah1,ah2,ah3, al0,al1,al2,al3;
            ldsm_x4(ah0,ah1,ah2,ah3, smem_u32(sQh + ro));
            ldsm_x4(al0,al1,al2,al3, smem_u32(sQl + ro));
            #pragma unroll
            for (int nt = 0; nt < 16; nt++) {
                int bo = (nt*8 + (l16 & 7))*SD_QP + k16 + ((l16 >> 3) & 1)*8;
                uint32_t bh0,bh1,bl0,bl1;
                ldsm_x2(bh0,bh1, smem_u32(sKh + bo));
                ldsm_x2(bl0,bl1, smem_u32(sKl + bo));
                mma_bf16(accS[nt], ah0,ah1,ah2,ah3, bh0,bh1);
                mma_bf16(accS[nt], ah0,ah1,ah2,ah3, bl0,bl1);
                mma_bf16(accS[nt], al0,al1,al2,al3, bh0,bh1);
            }
        }
        // mask tril + split-store S
        #pragma unroll
        for (int nt = 0; nt < 16; nt++) {
            int r0 = mrow + g, r1 = r0 + 8;
            int c0 = nt*8 + tg*2;
            float v00 = (c0     <= r0) ? accS[nt][0] : 0.f;
            float v01 = (c0 + 1 <= r0) ? accS[nt][1] : 0.f;
            float v10 = (c0     <= r1) ? accS[nt][2] : 0.f;
            float v11 = (c0 + 1 <= r1) ? accS[nt][3] : 0.f;
            __nv_bfloat16 h00 = __float2bfloat16(v00), h01 = __float2bfloat16(v01);
            __nv_bfloat16 h10 = __float2bfloat16(v10), h11 = __float2bfloat16(v11);
            *(uint32_t*)&sSh[r0*SD_SP + c0] =
                (uint32_t)__bfloat16_as_ushort(h00) | ((uint32_t)__bfloat16_as_ushort(h01) << 16);
            *(uint32_t*)&sSh[r1*SD_SP + c0] =
                (uint32_t)__bfloat16_as_ushort(h10) | ((uint32_t)__bfloat16_as_ushort(h11) << 16);
            *(uint32_t*)&sSl[r0*SD_SP + c0] =
                pack2(v00 - __bfloat162float(h00), v01 - __bfloat162float(h01));
            *(uint32_t*)&sSl[r1*SD_SP + c0] =
                pack2(v10 - __bfloat162float(h10), v11 - __bfloat162float(h11));
        }
    }
    __syncwarp();

    // phase 2: num = S*V + Qp*KV (3-pass split), scale, write bf16 hi/lo out
    {
        float acc2[8][4];
        #pragma unroll
        for (int nt = 0; nt < 8; nt++)
            #pragma unroll
            for (int r = 0; r < 4; r++) acc2[nt][r] = 0.f;

        #pragma unroll
        for (int k16 = 0; k16 < 128; k16 += 16) {
            int ro = (mrow + l16)*SD_SP + k16 + ahalf;
            uint32_t ah0,ah1,ah2,ah3, al0,al1,al2,al3;
            ldsm_x4(ah0,ah1,ah2,ah3, smem_u32(sSh + ro));
            ldsm_x4(al0,al1,al2,al3, smem_u32(sSl + ro));
            #pragma unroll
            for (int nt = 0; nt < 8; nt++) {
                int bo = (k16 + l16)*SD_QP + nt*8;
                uint32_t bh0,bh1,bl0,bl1;
                ldsm_x2_t(bh0,bh1, smem_u32(sVh + bo));
                ldsm_x2_t(bl0,bl1, smem_u32(sVl + bo));
                mma_bf16(acc2[nt], ah0,ah1,ah2,ah3, bh0,bh1);
                mma_bf16(acc2[nt], ah0,ah1,ah2,ah3, bl0,bl1);
                mma_bf16(acc2[nt], al0,al1,al2,al3, bh0,bh1);
            }
        }
        #pragma unroll
        for (int k16 = 0; k16 < 64; k16 += 16) {
            int ro = (mrow + l16)*SD_QP + k16 + ahalf;
            uint32_t ah0,ah1,ah2,ah3, al0,al1,al2,al3;
            ldsm_x4(ah0,ah1,ah2,ah3, smem_u32(sQh + ro));
            ldsm_x4(al0,al1,al2,al3, smem_u32(sQl + ro));
            #pragma unroll
            for (int nt = 0; nt < 8; nt++) {
                int bo = (k16 + l16)*SD_QP + nt*8;
                uint32_t bh0,bh1,bl0,bl1;
                ldsm_x2_t(bh0,bh1, smem_u32(sCh + bo));
                ldsm_x2_t(bl0,bl1, smem_u32(sCl + bo));
                mma_bf16(acc2[nt], ah0,ah1,ah2,ah3, bh0,bh1);
                mma_bf16(acc2[nt], ah0,ah1,ah2,ah3, bl0,bl1);
                mma_bf16(acc2[nt], al0,al1,al2,al3, bh0,bh1);
            }
        }

        const int r0 = mrow + g, r1 = r0 + 8;
        const float d0 = dinv[r0], d1 = dinv[r1];
        #pragma unroll
        for (int nt = 0; nt < 8; nt++) {
            int c0 = nt*8 + tg*2;
            float o00 = acc2[nt][0]*d0, o01 = acc2[nt][1]*d0;
            float o10 = acc2[nt][2]*d1, o11 = acc2[nt][3]*d1;
            size_t a0 = (t0 + r0)*1024 + h*64 + c0;
            size_t a1 = (t0 + r1)*1024 + h*64 + c0;
            __nv_bfloat16 h00 = __float2bfloat16(o00), h01 = __float2bfloat16(o01);
            __nv_bfloat16 h10 = __float2bfloat16(o10), h11 = __float2bfloat16(o11);
            *(uint32_t*)&g_ahi[a0] =
                (uint32_t)__bfloat16_as_ushort(h00) | ((uint32_t)__bfloat16_as_ushort(h01) << 16);
            *(uint32_t*)&g_ahi[a1] =
                (uint32_t)__bfloat16_as_ushort(h10) | ((uint32_t)__bfloat16_as_ushort(h11) << 16);
            *(uint32_t*)&g_alo[a0] =
                pack2(o00 - __bfloat162float(h00), o01 - __bfloat162float(h01));
            *(uint32_t*)&g_alo[a1] =
                pack2(o10 - __bfloat162float(h10), o11 - __bfloat162float(h11));
        }
    }
}

// ---------------- launch ------------------------------------------------------
extern "C" void kernel_launch(void* const* d_in, const int* in_sizes, int n_in,
                              void* d_out, int out_size)
{
    const float* hidden = (const float*)d_in[0];
    const float* cosg   = (const float*)d_in[1];
    const float* sing   = (const float*)d_in[2];
    const float* W_qkv  = (const float*)d_in[3];
    const float* W_o    = (const float*)d_in[4];
    const float* proj   = (const float*)d_in[5];
    float* out = (float*)d_out;

    static bool attr_done = false;
    if (!attr_done) {
        cudaFuncSetAttribute(chunkkv_kernel,
            cudaFuncAttributeMaxDynamicSharedMemorySize, 65536);
        cudaFuncSetAttribute(stage_d_kernel,
            cudaFuncAttributeMaxDynamicSharedMemorySize, SD_BYTES);
        cudaFuncSetAttribute(gemm_mma_kernel,
            cudaFuncAttributeMaxDynamicSharedMemorySize, GM_SMEM);
        attr_done = true;
    }

    float* qkv = nullptr; cudaGetSymbolAddress((void**)&qkv, g_qkv);
    __nv_bfloat16 *ahi, *alo, *w1hi, *w1lo, *w2hi, *w2lo;
    cudaGetSymbolAddress((void**)&ahi,  g_ahi);
    cudaGetSymbolAddress((void**)&alo,  g_alo);
    cudaGetSymbolAddress((void**)&w1hi, g_w1hi);
    cudaGetSymbolAddress((void**)&w1lo, g_w1lo);
    cudaGetSymbolAddress((void**)&w2hi, g_w2hi);
    cudaGetSymbolAddress((void**)&w2lo, g_w2lo);

    // 1. split-convert hidden + W_qkv, then QKV GEMM on tensor cores
    cvt_split_kernel<<<(MROWS*1024)/1024, 256>>>(hidden, ahi, alo, MROWS*1024);
    cvt_split_kernel<<<(2048*1024)/1024, 256>>>(W_qkv, w1hi, w1lo, 2048*1024);
    gemm_mma_kernel<<<dim3(QKVD/128, MROWS/128), 256, GM_SMEM>>>(
        ahi, alo, w1hi, w1lo, qkv, QKVD, 1024);

    // 2. rope + feature projection
    ropeproj_kernel<<<(MROWS*24)/64, 128>>>(cosg, sing, proj);
    // 3. z: parallel rowsum then scan
    kpsum_kernel<<<(MROWS*NKVH)/256, 256>>>();
    zscan_kernel<<<Bv*NKVH, 256>>>();
    // 4. per-chunk KV
    chunkkv_kernel<<<dim3(NCHUNK, Bv*NKVH), 256, 65536>>>();
    // 5. exclusive chunk prefix
    kvprefix_kernel<<<Bv*NKVH, 256>>>();
    // 6. causal combine -> writes bf16 hi/lo attn directly
    stage_d_kernel<<<dim3(NCHUNK, NHEAD, Bv), 256, SD_BYTES>>>();

    // 7. split-convert W_o, then output GEMM on tensor cores
    cvt_split_kernel<<<(1024*1024)/1024, 256>>>(W_o, w2hi, w2lo, 1024*1024);
    gemm_mma_kernel<<<dim3(1024/128, MROWS/128), 256, GM_SMEM>>>(
        ahi, alo, w2hi, w2lo, out, 1024, 1024);
}